// round 2
// baseline (speedup 1.0000x reference)
#include <cuda_runtime.h>
#include <math.h>

// Problem constants
#define B_BATCH 4
#define S_SEQ   1024
#define H_DIM   1024
#define I_DIM   768
#define E_NUM   8
#define K_TOP   2
#define T_TOK   (B_BATCH * S_SEQ)      // 4096
#define TKS     (T_TOK * K_TOP)        // 8192 slots

#define BM        128
#define MAX_TILES (TKS / BM + E_NUM)   // 72

// ---------------- device scratch (no allocations allowed) ----------------
__device__ int   g_is64;              // 1 if selected_experts is int64
__device__ int   g_ntiles;
__device__ int   g_tile_e[MAX_TILES];
__device__ int   g_tile_row[MAX_TILES];
__device__ int   g_tile_m[MAX_TILES];
__device__ int   g_tok[TKS];          // token index for each sorted slot position
__device__ int   g_slotpos[TKS];      // sorted position for slot (t*K + k)
__device__ float g_h[(size_t)TKS * I_DIM];   // silu(gate)*up, 25.2 MB
__device__ float g_y[(size_t)TKS * H_DIM];   // per-slot down output, 33.6 MB

// ---------------- dtype detection ----------------------------------------
// Reads the first 16KB of the selected_experts buffer (safe whether the
// buffer holds 8192 int32 = 32KB or 8192 int64 = 64KB). If ALL 2048 int64
// interpretations are in [0, E_NUM), the data is genuinely int64; an int32
// buffer viewed as int64 has (hi<<32 | lo) out of range unless every odd
// element is zero (probability ~8^-2048).
__global__ void detect_kernel(const long long* __restrict__ se64) {
    __shared__ int s_bad;
    if (threadIdx.x == 0) s_bad = 0;
    __syncthreads();
    int bad = 0;
    for (int i = threadIdx.x; i < 2048; i += blockDim.x) {
        long long v = se64[i];
        if (v < 0 || v >= E_NUM) bad = 1;
    }
    if (bad) atomicOr(&s_bad, 1);
    __syncthreads();
    if (threadIdx.x == 0) g_is64 = s_bad ? 0 : 1;
}

// ---------------- routing: histogram + tiles + position assignment -------
__global__ void route_kernel(const void* __restrict__ se_raw) {
    __shared__ int s_cnt[E_NUM];
    __shared__ int s_pos[E_NUM];
    const int is64 = g_is64;
    const int*       se32 = (const int*)se_raw;
    const long long* se64 = (const long long*)se_raw;
    int tid = threadIdx.x;
    if (tid < E_NUM) s_cnt[tid] = 0;
    __syncthreads();
    for (int s = tid; s < TKS; s += blockDim.x) {
        int e = is64 ? (int)se64[s] : se32[s];
        atomicAdd(&s_cnt[e], 1);
    }
    __syncthreads();
    if (tid == 0) {
        int off = 0, nt = 0;
        for (int e = 0; e < E_NUM; e++) {
            int c = s_cnt[e];
            s_pos[e] = off;
            for (int r = 0; r < c; r += BM) {
                g_tile_e[nt]   = e;
                g_tile_row[nt] = off + r;
                g_tile_m[nt]   = min(BM, c - r);
                nt++;
            }
            off += c;
        }
        g_ntiles = nt;
        for (int t = nt; t < MAX_TILES; t++) g_tile_m[t] = 0;
    }
    __syncthreads();
    for (int s = tid; s < TKS; s += blockDim.x) {
        int e = is64 ? (int)se64[s] : se32[s];
        int pos = atomicAdd(&s_pos[e], 1);
        g_tok[pos]    = s >> 1;     // K_TOP == 2
        g_slotpos[s]  = pos;
    }
}

// ---------------- GEMM1: fused gate+up + SiLU ----------------------------
// Tile: BM=128 rows (slots), BN=64 cols (I dim), BK=16 over H.
// 256 threads, thread tile 8x4, two accumulators (gate/up) sharing A.
__global__ __launch_bounds__(256) void gemm1_kernel(
    const float* __restrict__ x,
    const float* __restrict__ Wg,
    const float* __restrict__ Wu)
{
    int tile = blockIdx.y;
    if (tile >= g_ntiles) return;
    const int e    = g_tile_e[tile];
    const int row0 = g_tile_row[tile];
    const int mcnt = g_tile_m[tile];
    const int n0   = blockIdx.x * 64;

    __shared__ float As[16][BM];
    __shared__ float Bg[16][64];
    __shared__ float Bu[16][64];

    const int tid   = threadIdx.x;
    const int a_row = tid >> 1;
    const int a_col = (tid & 1) * 8;
    const int tok   = g_tok[row0 + min(a_row, mcnt - 1)];
    const float* a_ptr = x + (size_t)tok * H_DIM + a_col;

    const int b_row = tid >> 2;
    const int b_col = (tid & 3) * 4;
    const float* bg_ptr = Wg + ((size_t)e * I_DIM + n0 + b_row) * H_DIM + b_col;
    const float* bu_ptr = Wu + ((size_t)e * I_DIM + n0 + b_row) * H_DIM + b_col;

    const int ty = tid >> 4;   // 0..15 -> 8 rows each
    const int tx = tid & 15;   // 0..15 -> 4 cols each

    float accg[8][4], accu[8][4];
#pragma unroll
    for (int i = 0; i < 8; i++)
#pragma unroll
        for (int j = 0; j < 4; j++) { accg[i][j] = 0.f; accu[i][j] = 0.f; }

    for (int k0 = 0; k0 < H_DIM; k0 += 16) {
        float4 a0 = *(const float4*)(a_ptr + k0);
        float4 a1 = *(const float4*)(a_ptr + k0 + 4);
        float4 g4 = *(const float4*)(bg_ptr + k0);
        float4 u4 = *(const float4*)(bu_ptr + k0);
        __syncthreads();
        As[a_col + 0][a_row] = a0.x; As[a_col + 1][a_row] = a0.y;
        As[a_col + 2][a_row] = a0.z; As[a_col + 3][a_row] = a0.w;
        As[a_col + 4][a_row] = a1.x; As[a_col + 5][a_row] = a1.y;
        As[a_col + 6][a_row] = a1.z; As[a_col + 7][a_row] = a1.w;
        Bg[b_col + 0][b_row] = g4.x; Bg[b_col + 1][b_row] = g4.y;
        Bg[b_col + 2][b_row] = g4.z; Bg[b_col + 3][b_row] = g4.w;
        Bu[b_col + 0][b_row] = u4.x; Bu[b_col + 1][b_row] = u4.y;
        Bu[b_col + 2][b_row] = u4.z; Bu[b_col + 3][b_row] = u4.w;
        __syncthreads();
#pragma unroll
        for (int k = 0; k < 16; k++) {
            float a[8];
            *(float4*)(a)     = *(const float4*)&As[k][ty * 8];
            *(float4*)(a + 4) = *(const float4*)&As[k][ty * 8 + 4];
            float4 bgv = *(const float4*)&Bg[k][tx * 4];
            float4 buv = *(const float4*)&Bu[k][tx * 4];
            float bg_[4] = {bgv.x, bgv.y, bgv.z, bgv.w};
            float bu_[4] = {buv.x, buv.y, buv.z, buv.w};
#pragma unroll
            for (int i = 0; i < 8; i++) {
#pragma unroll
                for (int j = 0; j < 4; j++) {
                    accg[i][j] += a[i] * bg_[j];
                    accu[i][j] += a[i] * bu_[j];
                }
            }
        }
    }

#pragma unroll
    for (int i = 0; i < 8; i++) {
        int m = ty * 8 + i;
        if (m < mcnt) {
            float* hp = g_h + (size_t)(row0 + m) * I_DIM + n0 + tx * 4;
#pragma unroll
            for (int j = 0; j < 4; j++) {
                float g = accg[i][j];
                float s = 1.0f / (1.0f + expf(-g));
                hp[j] = g * s * accu[i][j];
            }
        }
    }
}

// ---------------- GEMM2: down projection ---------------------------------
// Tile: BM=128 rows (slots), BN=128 cols (H dim), BK=16 over I.
__global__ __launch_bounds__(256) void gemm2_kernel(const float* __restrict__ Wd)
{
    int tile = blockIdx.y;
    if (tile >= g_ntiles) return;
    const int e    = g_tile_e[tile];
    const int row0 = g_tile_row[tile];
    const int mcnt = g_tile_m[tile];
    const int n0   = blockIdx.x * 128;

    __shared__ float As[16][128];
    __shared__ float Bs[16][128];

    const int tid   = threadIdx.x;
    const int a_row = tid >> 1;
    const int a_col = (tid & 1) * 8;
    const float* a_ptr = g_h + (size_t)(row0 + min(a_row, mcnt - 1)) * I_DIM + a_col;

    const int b_row = tid >> 1;
    const int b_col = (tid & 1) * 8;
    const float* b_ptr = Wd + ((size_t)e * H_DIM + n0 + b_row) * I_DIM + b_col;

    const int ty = tid >> 4;
    const int tx = tid & 15;

    float acc[8][8];
#pragma unroll
    for (int i = 0; i < 8; i++)
#pragma unroll
        for (int j = 0; j < 8; j++) acc[i][j] = 0.f;

    for (int k0 = 0; k0 < I_DIM; k0 += 16) {
        float4 a0 = *(const float4*)(a_ptr + k0);
        float4 a1 = *(const float4*)(a_ptr + k0 + 4);
        float4 b0 = *(const float4*)(b_ptr + k0);
        float4 b1 = *(const float4*)(b_ptr + k0 + 4);
        __syncthreads();
        As[a_col + 0][a_row] = a0.x; As[a_col + 1][a_row] = a0.y;
        As[a_col + 2][a_row] = a0.z; As[a_col + 3][a_row] = a0.w;
        As[a_col + 4][a_row] = a1.x; As[a_col + 5][a_row] = a1.y;
        As[a_col + 6][a_row] = a1.z; As[a_col + 7][a_row] = a1.w;
        Bs[b_col + 0][b_row] = b0.x; Bs[b_col + 1][b_row] = b0.y;
        Bs[b_col + 2][b_row] = b0.z; Bs[b_col + 3][b_row] = b0.w;
        Bs[b_col + 4][b_row] = b1.x; Bs[b_col + 5][b_row] = b1.y;
        Bs[b_col + 6][b_row] = b1.z; Bs[b_col + 7][b_row] = b1.w;
        __syncthreads();
#pragma unroll
        for (int k = 0; k < 16; k++) {
            float a[8], b[8];
            *(float4*)(a)     = *(const float4*)&As[k][ty * 8];
            *(float4*)(a + 4) = *(const float4*)&As[k][ty * 8 + 4];
            *(float4*)(b)     = *(const float4*)&Bs[k][tx * 8];
            *(float4*)(b + 4) = *(const float4*)&Bs[k][tx * 8 + 4];
#pragma unroll
            for (int i = 0; i < 8; i++)
#pragma unroll
                for (int j = 0; j < 8; j++)
                    acc[i][j] += a[i] * b[j];
        }
    }

#pragma unroll
    for (int i = 0; i < 8; i++) {
        int m = ty * 8 + i;
        if (m < mcnt) {
            float* yp = g_y + (size_t)(row0 + m) * H_DIM + n0 + tx * 8;
            *(float4*)(yp)     = make_float4(acc[i][0], acc[i][1], acc[i][2], acc[i][3]);
            *(float4*)(yp + 4) = make_float4(acc[i][4], acc[i][5], acc[i][6], acc[i][7]);
        }
    }
}

// ---------------- combine: out[t] = w0*Y[slot0] + w1*Y[slot1] -------------
__global__ void combine_kernel(const float* __restrict__ rw, float4* __restrict__ out)
{
    int idx = blockIdx.x * blockDim.x + threadIdx.x;   // T*H/4 threads
    int t = idx >> 8;          // H/4 = 256 float4 per token
    int c = idx & 255;
    float w0 = rw[2 * t];
    float w1 = rw[2 * t + 1];
    int p0 = g_slotpos[2 * t];
    int p1 = g_slotpos[2 * t + 1];
    const float4* y = (const float4*)g_y;
    float4 y0 = y[(size_t)p0 * 256 + c];
    float4 y1 = y[(size_t)p1 * 256 + c];
    out[idx] = make_float4(w0 * y0.x + w1 * y1.x,
                           w0 * y0.y + w1 * y1.y,
                           w0 * y0.z + w1 * y1.z,
                           w0 * y0.w + w1 * y1.w);
}

// ---------------- launch ---------------------------------------------------
extern "C" void kernel_launch(void* const* d_in, const int* in_sizes, int n_in,
                              void* d_out, int out_size)
{
    const float* x   = (const float*)d_in[0];      // [B,S,H]
    const float* rw  = (const float*)d_in[1];      // [B,S,K]
    const void*  se  = d_in[2];                    // [B,S,K] int32 or int64
    const float* Wg  = (const float*)d_in[3];      // [E,I,H]
    const float* Wu  = (const float*)d_in[4];      // [E,I,H]
    const float* Wd  = (const float*)d_in[5];      // [E,H,I]
    float*       out = (float*)d_out;              // [B,S,H]

    detect_kernel<<<1, 256>>>((const long long*)se);
    route_kernel<<<1, 256>>>(se);
    gemm1_kernel<<<dim3(I_DIM / 64, MAX_TILES), 256>>>(x, Wg, Wu);
    gemm2_kernel<<<dim3(H_DIM / 128, MAX_TILES), 256>>>(Wd);
    combine_kernel<<<(T_TOK * H_DIM / 4) / 256, 256>>>(rw, (float4*)out);
    (void)in_sizes; (void)n_in; (void)out_size;
}

// round 4
// speedup vs baseline: 1.4791x; 1.4791x over previous
#include <cuda_runtime.h>
#include <cuda_bf16.h>
#include <cstdint>
#include <math.h>

// Problem constants
#define B_BATCH 4
#define S_SEQ   1024
#define H_DIM   1024
#define I_DIM   768
#define E_NUM   8
#define T_TOK   4096
#define TKS     8192

#define BM        128
#define MAX_TILES 72
#define WELEM     (E_NUM * I_DIM * H_DIM)     // 6291456

// ---------------- device scratch ----------------
__device__ int      g_is64;
__device__ int      g_ntiles;
__device__ int      g_tile_e[MAX_TILES];
__device__ int      g_tile_row[MAX_TILES];
__device__ int      g_tile_m[MAX_TILES];
__device__ int      g_tok[TKS];
__device__ int      g_slotpos[TKS];
// hi/lo bf16 splits (packed bf16x2 per u32)
__device__ uint32_t g_x_hi[T_TOK * H_DIM / 2];
__device__ uint32_t g_x_lo[T_TOK * H_DIM / 2];
__device__ uint32_t g_wg_hi[WELEM / 2];
__device__ uint32_t g_wg_lo[WELEM / 2];
__device__ uint32_t g_wu_hi[WELEM / 2];
__device__ uint32_t g_wu_lo[WELEM / 2];
__device__ uint32_t g_wd_hi[WELEM / 2];
__device__ uint32_t g_wd_lo[WELEM / 2];
__device__ uint32_t g_h_hi[(size_t)TKS * I_DIM / 2];
__device__ uint32_t g_h_lo[(size_t)TKS * I_DIM / 2];
__device__ float    g_y[(size_t)TKS * H_DIM];

// ---------------- helpers ----------------
__device__ __forceinline__ uint32_t smem_u32(const void* p) {
    uint32_t r;
    asm("{ .reg .u64 t; cvta.to.shared.u64 t, %1; cvt.u32.u64 %0, t; }"
        : "=r"(r) : "l"(p));
    return r;
}
__device__ __forceinline__ uint32_t lds32(uint32_t a) {
    uint32_t v;
    asm volatile("ld.shared.b32 %0, [%1];" : "=r"(v) : "r"(a));
    return v;
}
__device__ __forceinline__ void cp16(uint32_t dst, const void* src) {
    asm volatile("cp.async.cg.shared.global [%0], [%1], 16;"
                 :: "r"(dst), "l"(__cvta_generic_to_global(src)) : "memory");
}
#define CP_COMMIT() asm volatile("cp.async.commit_group;" ::: "memory")

__device__ __forceinline__ void mma_bf16(float* d, const uint32_t* a, const uint32_t* b) {
    asm volatile(
        "mma.sync.aligned.m16n8k16.row.col.f32.bf16.bf16.f32 "
        "{%0,%1,%2,%3}, {%4,%5,%6,%7}, {%8,%9}, {%0,%1,%2,%3};"
        : "+f"(d[0]), "+f"(d[1]), "+f"(d[2]), "+f"(d[3])
        : "r"(a[0]), "r"(a[1]), "r"(a[2]), "r"(a[3]), "r"(b[0]), "r"(b[1]));
}

__device__ __forceinline__ uint32_t pack_bf16(float a, float b) {
    __nv_bfloat162 t = __halves2bfloat162(__float2bfloat16_rn(a), __float2bfloat16_rn(b));
    return *reinterpret_cast<uint32_t*>(&t);
}

// ---------------- dtype detect + routing (proven) ----------------
__global__ void detect_kernel(const long long* __restrict__ se64) {
    __shared__ int s_bad;
    if (threadIdx.x == 0) s_bad = 0;
    __syncthreads();
    int bad = 0;
    for (int i = threadIdx.x; i < 2048; i += blockDim.x) {
        long long v = se64[i];
        if (v < 0 || v >= E_NUM) bad = 1;
    }
    if (bad) atomicOr(&s_bad, 1);
    __syncthreads();
    if (threadIdx.x == 0) g_is64 = s_bad ? 0 : 1;
}

__global__ void route_kernel(const void* __restrict__ se_raw) {
    __shared__ int s_cnt[E_NUM];
    __shared__ int s_pos[E_NUM];
    const int is64 = g_is64;
    const int*       se32 = (const int*)se_raw;
    const long long* se64 = (const long long*)se_raw;
    int tid = threadIdx.x;
    if (tid < E_NUM) s_cnt[tid] = 0;
    __syncthreads();
    for (int s = tid; s < TKS; s += blockDim.x) {
        int e = is64 ? (int)se64[s] : se32[s];
        atomicAdd(&s_cnt[e], 1);
    }
    __syncthreads();
    if (tid == 0) {
        int off = 0, nt = 0;
        for (int e = 0; e < E_NUM; e++) {
            int c = s_cnt[e];
            s_pos[e] = off;
            for (int r = 0; r < c; r += BM) {
                g_tile_e[nt]   = e;
                g_tile_row[nt] = off + r;
                g_tile_m[nt]   = min(BM, c - r);
                nt++;
            }
            off += c;
        }
        g_ntiles = nt;
    }
    __syncthreads();
    for (int s = tid; s < TKS; s += blockDim.x) {
        int e = is64 ? (int)se64[s] : se32[s];
        int pos = atomicAdd(&s_pos[e], 1);
        g_tok[pos]   = s >> 1;
        g_slotpos[s] = pos;
    }
}

// ---------------- fp32 -> bf16 hi/lo split ----------------
// which: 0=x, 1=Wg, 2=Wu, 3=Wd.  n4 = element_count / 4.
__global__ void split_kernel(const float4* __restrict__ src, int which, int n4) {
    uint2* hi; uint2* lo;
    switch (which) {
        case 0: hi = (uint2*)g_x_hi;  lo = (uint2*)g_x_lo;  break;
        case 1: hi = (uint2*)g_wg_hi; lo = (uint2*)g_wg_lo; break;
        case 2: hi = (uint2*)g_wu_hi; lo = (uint2*)g_wu_lo; break;
        default:hi = (uint2*)g_wd_hi; lo = (uint2*)g_wd_lo; break;
    }
    int i = blockIdx.x * blockDim.x + threadIdx.x;
    if (i >= n4) return;
    float4 v = src[i];
    __nv_bfloat16 h0 = __float2bfloat16_rn(v.x), h1 = __float2bfloat16_rn(v.y);
    __nv_bfloat16 h2 = __float2bfloat16_rn(v.z), h3 = __float2bfloat16_rn(v.w);
    float r0 = v.x - __bfloat162float(h0), r1 = v.y - __bfloat162float(h1);
    float r2 = v.z - __bfloat162float(h2), r3 = v.w - __bfloat162float(h3);
    __nv_bfloat162 ph0 = __halves2bfloat162(h0, h1), ph1 = __halves2bfloat162(h2, h3);
    hi[i] = make_uint2(*reinterpret_cast<uint32_t*>(&ph0), *reinterpret_cast<uint32_t*>(&ph1));
    lo[i] = make_uint2(pack_bf16(r0, r1), pack_bf16(r2, r3));
}

// ---------------- GEMM1: gate+up fused, SiLU epilogue (HMMA) -------------
// CTA 128x64, K=1024 in 32 chunks of 32. 8 warps (4m x 2n), warp 32x32.
// smem/buffer: A_hi@0, A_lo@10240, Bg_hi@20480, Bg_lo@25600, Bu_hi@30720,
// Bu_lo@35840; buffer stride 40960; rows padded to 80B.
__global__ __launch_bounds__(256) void gemm1_hmma() {
    extern __shared__ char dsm[];
    const int tile = blockIdx.y;
    if (tile >= g_ntiles) return;
    const int e    = g_tile_e[tile];
    const int row0 = g_tile_row[tile];
    const int mcnt = g_tile_m[tile];
    const int n0   = blockIdx.x * 64;
    const int tid  = threadIdx.x, lane = tid & 31, wid = tid >> 5;
    const int wm   = wid & 3, wn = wid >> 2;
    const uint32_t sbase = smem_u32(dsm);

    // per-thread async-copy jobs
    const int ar = tid & 127, awhich = tid >> 7;
    const int tokA = g_tok[row0 + min(ar, mcnt - 1)];
    const char* asrc = (const char*)(awhich ? g_x_lo : g_x_hi)
                       + (size_t)tokA * (H_DIM * 2);
    const uint32_t adst = sbase + awhich * 10240 + ar * 80;

    const int bmat = tid >> 6, bn = tid & 63;
    const uint32_t* bb = (bmat == 0) ? g_wg_hi : (bmat == 1) ? g_wg_lo
                        : (bmat == 2) ? g_wu_hi : g_wu_lo;
    const char* bsrc = (const char*)bb + (size_t)(e * I_DIM + n0 + bn) * (H_DIM * 2);
    const uint32_t bdst = sbase + 20480 + bmat * 5120 + bn * 80;

    float accg[32], accu[32];
#pragma unroll
    for (int i = 0; i < 32; i++) { accg[i] = 0.f; accu[i] = 0.f; }

    const int NC = H_DIM / 32;   // 32
#pragma unroll
    for (int j = 0; j < 4; j++) cp16(adst + j * 16, asrc + j * 16);
#pragma unroll
    for (int j = 0; j < 4; j++) cp16(bdst + j * 16, bsrc + j * 16);
    CP_COMMIT();

    for (int c = 0; c < NC; c++) {
        if (c + 1 < NC) {
            const uint32_t bo = ((c + 1) & 1) * 40960;
            const char* as = asrc + (size_t)(c + 1) * 64;
            const char* bs = bsrc + (size_t)(c + 1) * 64;
#pragma unroll
            for (int j = 0; j < 4; j++) cp16(adst + bo + j * 16, as + j * 16);
#pragma unroll
            for (int j = 0; j < 4; j++) cp16(bdst + bo + j * 16, bs + j * 16);
            CP_COMMIT();
            asm volatile("cp.async.wait_group 1;" ::: "memory");
        } else {
            asm volatile("cp.async.wait_group 0;" ::: "memory");
        }
        __syncthreads();
        const uint32_t buf = sbase + (c & 1) * 40960;
#pragma unroll
        for (int kk = 0; kk < 2; kk++) {
            const uint32_t colb = kk * 32 + (lane & 3) * 4;
            uint32_t Ah[2][4], Al[2][4];
#pragma unroll
            for (int mt = 0; mt < 2; mt++) {
                uint32_t a = buf + (wm * 32 + mt * 16 + (lane >> 2)) * 80 + colb;
                Ah[mt][0] = lds32(a);       Ah[mt][1] = lds32(a + 640);
                Ah[mt][2] = lds32(a + 16);  Ah[mt][3] = lds32(a + 656);
                uint32_t al = a + 10240;
                Al[mt][0] = lds32(al);      Al[mt][1] = lds32(al + 640);
                Al[mt][2] = lds32(al + 16); Al[mt][3] = lds32(al + 656);
            }
            {   // gate
                uint32_t Bh[4][2], Bl[4][2];
#pragma unroll
                for (int nt = 0; nt < 4; nt++) {
                    uint32_t a = buf + 20480 + (wn * 32 + nt * 8 + (lane >> 2)) * 80 + colb;
                    Bh[nt][0] = lds32(a);        Bh[nt][1] = lds32(a + 16);
                    Bl[nt][0] = lds32(a + 5120); Bl[nt][1] = lds32(a + 5136);
                }
#pragma unroll
                for (int mt = 0; mt < 2; mt++)
#pragma unroll
                for (int nt = 0; nt < 4; nt++) {
                    float* d = accg + mt * 16 + nt * 4;
                    mma_bf16(d, Ah[mt], Bh[nt]);
                    mma_bf16(d, Ah[mt], Bl[nt]);
                    mma_bf16(d, Al[mt], Bh[nt]);
                }
            }
            {   // up
                uint32_t Bh[4][2], Bl[4][2];
#pragma unroll
                for (int nt = 0; nt < 4; nt++) {
                    uint32_t a = buf + 30720 + (wn * 32 + nt * 8 + (lane >> 2)) * 80 + colb;
                    Bh[nt][0] = lds32(a);        Bh[nt][1] = lds32(a + 16);
                    Bl[nt][0] = lds32(a + 5120); Bl[nt][1] = lds32(a + 5136);
                }
#pragma unroll
                for (int mt = 0; mt < 2; mt++)
#pragma unroll
                for (int nt = 0; nt < 4; nt++) {
                    float* d = accu + mt * 16 + nt * 4;
                    mma_bf16(d, Ah[mt], Bh[nt]);
                    mma_bf16(d, Ah[mt], Bl[nt]);
                    mma_bf16(d, Al[mt], Bh[nt]);
                }
            }
        }
        __syncthreads();
    }

    // epilogue: h = silu(g) * u, split hi/lo, write packed bf16x2
#pragma unroll
    for (int mt = 0; mt < 2; mt++)
#pragma unroll
    for (int nt = 0; nt < 4; nt++) {
        const int mB   = wm * 32 + mt * 16 + (lane >> 2);
        const int gcol = n0 + wn * 32 + nt * 8 + (lane & 3) * 2;
        const float* dg = accg + mt * 16 + nt * 4;
        const float* du = accu + mt * 16 + nt * 4;
#pragma unroll
        for (int half = 0; half < 2; half++) {
            const int m = mB + half * 8;
            if (m < mcnt) {
                float g0 = dg[half * 2], g1 = dg[half * 2 + 1];
                float u0 = du[half * 2], u1 = du[half * 2 + 1];
                float h0 = g0 / (1.f + __expf(-g0)) * u0;
                float h1 = g1 / (1.f + __expf(-g1)) * u1;
                __nv_bfloat16 hh0 = __float2bfloat16_rn(h0);
                __nv_bfloat16 hh1 = __float2bfloat16_rn(h1);
                float r0 = h0 - __bfloat162float(hh0);
                float r1 = h1 - __bfloat162float(hh1);
                __nv_bfloat162 th = __halves2bfloat162(hh0, hh1);
                size_t o = ((size_t)(row0 + m) * I_DIM + gcol) >> 1;
                g_h_hi[o] = *reinterpret_cast<uint32_t*>(&th);
                g_h_lo[o] = pack_bf16(r0, r1);
            }
        }
    }
}

// ---------------- GEMM2: down projection (HMMA) --------------------------
// CTA 128x64, K=768 in 24 chunks of 32.
// smem/buffer: A_hi@0, A_lo@10240, B_hi@20480, B_lo@25600; stride 30720.
__global__ __launch_bounds__(256) void gemm2_hmma() {
    extern __shared__ char dsm[];
    const int tile = blockIdx.y;
    if (tile >= g_ntiles) return;
    const int e    = g_tile_e[tile];
    const int row0 = g_tile_row[tile];
    const int mcnt = g_tile_m[tile];
    const int n0   = blockIdx.x * 64;
    const int tid  = threadIdx.x, lane = tid & 31, wid = tid >> 5;
    const int wm   = wid & 3, wn = wid >> 2;
    const uint32_t sbase = smem_u32(dsm);

    const int ar = tid & 127, awhich = tid >> 7;
    const int arow = row0 + min(ar, mcnt - 1);
    const char* asrc = (const char*)(awhich ? g_h_lo : g_h_hi)
                       + (size_t)arow * (I_DIM * 2);
    const uint32_t adst = sbase + awhich * 10240 + ar * 80;

    const bool hasB = (tid < 128);
    const int bmat = (tid >> 6) & 1, bn = tid & 63;
    const char* bsrc = (const char*)(bmat ? g_wd_lo : g_wd_hi)
                       + (size_t)(e * H_DIM + n0 + bn) * (I_DIM * 2);
    const uint32_t bdst = sbase + 20480 + bmat * 5120 + bn * 80;

    float acc[32];
#pragma unroll
    for (int i = 0; i < 32; i++) acc[i] = 0.f;

    const int NC = I_DIM / 32;   // 24
#pragma unroll
    for (int j = 0; j < 4; j++) cp16(adst + j * 16, asrc + j * 16);
    if (hasB) {
#pragma unroll
        for (int j = 0; j < 4; j++) cp16(bdst + j * 16, bsrc + j * 16);
    }
    CP_COMMIT();

    for (int c = 0; c < NC; c++) {
        if (c + 1 < NC) {
            const uint32_t bo = ((c + 1) & 1) * 30720;
            const char* as = asrc + (size_t)(c + 1) * 64;
#pragma unroll
            for (int j = 0; j < 4; j++) cp16(adst + bo + j * 16, as + j * 16);
            if (hasB) {
                const char* bs = bsrc + (size_t)(c + 1) * 64;
#pragma unroll
                for (int j = 0; j < 4; j++) cp16(bdst + bo + j * 16, bs + j * 16);
            }
            CP_COMMIT();
            asm volatile("cp.async.wait_group 1;" ::: "memory");
        } else {
            asm volatile("cp.async.wait_group 0;" ::: "memory");
        }
        __syncthreads();
        const uint32_t buf = sbase + (c & 1) * 30720;
#pragma unroll
        for (int kk = 0; kk < 2; kk++) {
            const uint32_t colb = kk * 32 + (lane & 3) * 4;
            uint32_t Ah[2][4], Al[2][4];
#pragma unroll
            for (int mt = 0; mt < 2; mt++) {
                uint32_t a = buf + (wm * 32 + mt * 16 + (lane >> 2)) * 80 + colb;
                Ah[mt][0] = lds32(a);       Ah[mt][1] = lds32(a + 640);
                Ah[mt][2] = lds32(a + 16);  Ah[mt][3] = lds32(a + 656);
                uint32_t al = a + 10240;
                Al[mt][0] = lds32(al);      Al[mt][1] = lds32(al + 640);
                Al[mt][2] = lds32(al + 16); Al[mt][3] = lds32(al + 656);
            }
            uint32_t Bh[4][2], Bl[4][2];
#pragma unroll
            for (int nt = 0; nt < 4; nt++) {
                uint32_t a = buf + 20480 + (wn * 32 + nt * 8 + (lane >> 2)) * 80 + colb;
                Bh[nt][0] = lds32(a);        Bh[nt][1] = lds32(a + 16);
                Bl[nt][0] = lds32(a + 5120); Bl[nt][1] = lds32(a + 5136);
            }
#pragma unroll
            for (int mt = 0; mt < 2; mt++)
#pragma unroll
            for (int nt = 0; nt < 4; nt++) {
                float* d = acc + mt * 16 + nt * 4;
                mma_bf16(d, Ah[mt], Bh[nt]);
                mma_bf16(d, Ah[mt], Bl[nt]);
                mma_bf16(d, Al[mt], Bh[nt]);
            }
        }
        __syncthreads();
    }

#pragma unroll
    for (int mt = 0; mt < 2; mt++)
#pragma unroll
    for (int nt = 0; nt < 4; nt++) {
        const int mB   = wm * 32 + mt * 16 + (lane >> 2);
        const int gcol = n0 + wn * 32 + nt * 8 + (lane & 3) * 2;
        const float* d = acc + mt * 16 + nt * 4;
#pragma unroll
        for (int half = 0; half < 2; half++) {
            const int m = mB + half * 8;
            if (m < mcnt) {
                float2 v = make_float2(d[half * 2], d[half * 2 + 1]);
                *(float2*)(g_y + (size_t)(row0 + m) * H_DIM + gcol) = v;
            }
        }
    }
}

// ---------------- combine -------------------------------------------------
__global__ void combine_kernel(const float* __restrict__ rw, float4* __restrict__ out)
{
    int idx = blockIdx.x * blockDim.x + threadIdx.x;
    int t = idx >> 8;
    int c = idx & 255;
    float w0 = rw[2 * t];
    float w1 = rw[2 * t + 1];
    int p0 = g_slotpos[2 * t];
    int p1 = g_slotpos[2 * t + 1];
    const float4* y = (const float4*)g_y;
    float4 y0 = y[(size_t)p0 * 256 + c];
    float4 y1 = y[(size_t)p1 * 256 + c];
    out[idx] = make_float4(w0 * y0.x + w1 * y1.x,
                           w0 * y0.y + w1 * y1.y,
                           w0 * y0.z + w1 * y1.z,
                           w0 * y0.w + w1 * y1.w);
}

// ---------------- launch ---------------------------------------------------
extern "C" void kernel_launch(void* const* d_in, const int* in_sizes, int n_in,
                              void* d_out, int out_size)
{
    const float* x   = (const float*)d_in[0];
    const float* rw  = (const float*)d_in[1];
    const void*  se  = d_in[2];
    const float* Wg  = (const float*)d_in[3];
    const float* Wu  = (const float*)d_in[4];
    const float* Wd  = (const float*)d_in[5];
    float*       out = (float*)d_out;

    const int SM1 = 2 * 40960;   // 81920
    const int SM2 = 2 * 30720;   // 61440
    cudaFuncSetAttribute(gemm1_hmma, cudaFuncAttributeMaxDynamicSharedMemorySize, SM1);
    cudaFuncSetAttribute(gemm2_hmma, cudaFuncAttributeMaxDynamicSharedMemorySize, SM2);

    detect_kernel<<<1, 256>>>((const long long*)se);
    route_kernel<<<1, 256>>>(se);

    const int xn4 = T_TOK * H_DIM / 4;   // 1048576
    const int wn4 = WELEM / 4;           // 1572864
    split_kernel<<<xn4 / 256, 256>>>((const float4*)x, 0, xn4);
    split_kernel<<<wn4 / 256, 256>>>((const float4*)Wg, 1, wn4);
    split_kernel<<<wn4 / 256, 256>>>((const float4*)Wu, 2, wn4);
    split_kernel<<<wn4 / 256, 256>>>((const float4*)Wd, 3, wn4);

    gemm1_hmma<<<dim3(I_DIM / 64, MAX_TILES), 256, SM1>>>();
    gemm2_hmma<<<dim3(H_DIM / 64, MAX_TILES), 256, SM2>>>();
    combine_kernel<<<(T_TOK * H_DIM / 4) / 256, 256>>>(rw, (float4*)out);
    (void)in_sizes; (void)n_in; (void)out_size;
}

// round 5
// speedup vs baseline: 1.7734x; 1.1989x over previous
#include <cuda_runtime.h>
#include <cuda_fp16.h>
#include <cstdint>
#include <math.h>

// Problem constants
#define B_BATCH 4
#define S_SEQ   1024
#define H_DIM   1024
#define I_DIM   768
#define E_NUM   8
#define T_TOK   4096
#define TKS     8192

#define BM        128
#define MAX_TILES 72
#define WELEM     (E_NUM * I_DIM * H_DIM)     // 6291456

// ---------------- device scratch (fp16 packed as uint32 pairs) -----------
__device__ int      g_is64;
__device__ int      g_ntiles;
__device__ int      g_tile_e[MAX_TILES];
__device__ int      g_tile_row[MAX_TILES];
__device__ int      g_tile_m[MAX_TILES];
__device__ int      g_tok[TKS];
__device__ int      g_slotpos[TKS];
__device__ uint32_t g_x_hi[T_TOK * H_DIM / 2];       // fp16x2
__device__ uint32_t g_x_lo[T_TOK * H_DIM / 2];
__device__ uint32_t g_wg[WELEM / 2];                 // single fp16
__device__ uint32_t g_wu[WELEM / 2];
__device__ uint32_t g_wd[WELEM / 2];
__device__ uint32_t g_h_hi[(size_t)TKS * I_DIM / 2];
__device__ uint32_t g_h_lo[(size_t)TKS * I_DIM / 2];
__device__ float    g_y[(size_t)TKS * H_DIM];

// ---------------- helpers ----------------
__device__ __forceinline__ uint32_t smem_u32(const void* p) {
    uint32_t r;
    asm("{ .reg .u64 t; cvta.to.shared.u64 t, %1; cvt.u32.u64 %0, t; }"
        : "=r"(r) : "l"(p));
    return r;
}
__device__ __forceinline__ void cp16(uint32_t dst, const void* src) {
    asm volatile("cp.async.cg.shared.global [%0], [%1], 16;"
                 :: "r"(dst), "l"(__cvta_generic_to_global(src)) : "memory");
}
#define CP_COMMIT() asm volatile("cp.async.commit_group;" ::: "memory")

__device__ __forceinline__ void ldmx4(uint32_t* r, uint32_t a) {
    asm volatile("ldmatrix.sync.aligned.m8n8.x4.shared.b16 {%0,%1,%2,%3}, [%4];"
                 : "=r"(r[0]), "=r"(r[1]), "=r"(r[2]), "=r"(r[3]) : "r"(a));
}
__device__ __forceinline__ void mma_f16(float* d, const uint32_t* a,
                                        uint32_t b0, uint32_t b1) {
    asm volatile(
        "mma.sync.aligned.m16n8k16.row.col.f32.f16.f16.f32 "
        "{%0,%1,%2,%3}, {%4,%5,%6,%7}, {%8,%9}, {%0,%1,%2,%3};"
        : "+f"(d[0]), "+f"(d[1]), "+f"(d[2]), "+f"(d[3])
        : "r"(a[0]), "r"(a[1]), "r"(a[2]), "r"(a[3]), "r"(b0), "r"(b1));
}
__device__ __forceinline__ uint32_t pack_f16(float a, float b) {
    __half2 t = __floats2half2_rn(a, b);
    return *reinterpret_cast<uint32_t*>(&t);
}

// ---------------- dtype detect + routing (proven) ----------------
__global__ void detect_kernel(const long long* __restrict__ se64) {
    __shared__ int s_bad;
    if (threadIdx.x == 0) s_bad = 0;
    __syncthreads();
    int bad = 0;
    for (int i = threadIdx.x; i < 2048; i += blockDim.x) {
        long long v = se64[i];
        if (v < 0 || v >= E_NUM) bad = 1;
    }
    if (bad) atomicOr(&s_bad, 1);
    __syncthreads();
    if (threadIdx.x == 0) g_is64 = s_bad ? 0 : 1;
}

__global__ void route_kernel(const void* __restrict__ se_raw) {
    __shared__ int s_cnt[E_NUM];
    __shared__ int s_pos[E_NUM];
    const int is64 = g_is64;
    const int*       se32 = (const int*)se_raw;
    const long long* se64 = (const long long*)se_raw;
    int tid = threadIdx.x;
    if (tid < E_NUM) s_cnt[tid] = 0;
    __syncthreads();
    for (int s = tid; s < TKS; s += blockDim.x) {
        int e = is64 ? (int)se64[s] : se32[s];
        atomicAdd(&s_cnt[e], 1);
    }
    __syncthreads();
    if (tid == 0) {
        int off = 0, nt = 0;
        for (int e = 0; e < E_NUM; e++) {
            int c = s_cnt[e];
            s_pos[e] = off;
            for (int r = 0; r < c; r += BM) {
                g_tile_e[nt]   = e;
                g_tile_row[nt] = off + r;
                g_tile_m[nt]   = min(BM, c - r);
                nt++;
            }
            off += c;
        }
        g_ntiles = nt;
    }
    __syncthreads();
    for (int s = tid; s < TKS; s += blockDim.x) {
        int e = is64 ? (int)se64[s] : se32[s];
        int pos = atomicAdd(&s_pos[e], 1);
        g_tok[pos]   = s >> 1;
        g_slotpos[s] = pos;
    }
}

// ---------------- prep: x -> fp16 hi/lo split ----------------
__global__ void split_x(const float4* __restrict__ src, int n4) {
    int i = blockIdx.x * blockDim.x + threadIdx.x;
    if (i >= n4) return;
    float4 v = src[i];
    __half h0 = __float2half_rn(v.x), h1 = __float2half_rn(v.y);
    __half h2 = __float2half_rn(v.z), h3 = __float2half_rn(v.w);
    float r0 = v.x - __half2float(h0), r1 = v.y - __half2float(h1);
    float r2 = v.z - __half2float(h2), r3 = v.w - __half2float(h3);
    __half2 a = __halves2half2(h0, h1), b = __halves2half2(h2, h3);
    ((uint2*)g_x_hi)[i] = make_uint2(*reinterpret_cast<uint32_t*>(&a),
                                     *reinterpret_cast<uint32_t*>(&b));
    ((uint2*)g_x_lo)[i] = make_uint2(pack_f16(r0, r1), pack_f16(r2, r3));
}

// ---------------- prep: weights -> single fp16 ----------------
__global__ void cvt_w(const float4* __restrict__ src, int which, int n4) {
    uint2* dst = (which == 1) ? (uint2*)g_wg : (which == 2) ? (uint2*)g_wu : (uint2*)g_wd;
    int i = blockIdx.x * blockDim.x + threadIdx.x;
    if (i >= n4) return;
    float4 v = src[i];
    dst[i] = make_uint2(pack_f16(v.x, v.y), pack_f16(v.z, v.w));
}

// ---------------- GEMM1: gate+up fused, SiLU epilogue --------------------
// CTA 128x64, K=1024 in 32 chunks of 32 (fp16, 64B/row/chunk, 80B pitch).
// smem/buffer: A_hi@0 (10240), A_lo@10240, Bg@20480 (5120), Bu@25600.
// Buffer stride 30720, double buffered = 61440.
__global__ __launch_bounds__(256) void gemm1_hmma() {
    extern __shared__ char dsm[];
    const int tile = blockIdx.y;
    if (tile >= g_ntiles) return;
    const int e    = g_tile_e[tile];
    const int row0 = g_tile_row[tile];
    const int mcnt = g_tile_m[tile];
    const int n0   = blockIdx.x * 64;
    const int tid  = threadIdx.x, lane = tid & 31, wid = tid >> 5;
    const int wm   = wid & 3, wn = wid >> 2;
    const uint32_t sbase = smem_u32(dsm);

    // A copy job: (row, part) per thread; 4 x cp16 (64B)
    const int ar = tid & 127, apart = tid >> 7;
    const int tokA = g_tok[row0 + min(ar, mcnt - 1)];
    const char* asrc = (const char*)(apart ? g_x_lo : g_x_hi) + (size_t)tokA * (H_DIM * 2);
    const uint32_t adst = sbase + apart * 10240 + ar * 80;
    // B copy job: row (0..127: 0-63 gate, 64-127 up), 2 x cp16
    const int brow = tid >> 1;
    const uint32_t jb = (tid & 1) * 32;
    const bool bg = brow < 64;
    const char* bsrc = (const char*)(bg ? g_wg : g_wu)
        + (size_t)(e * I_DIM + n0 + (bg ? brow : brow - 64)) * (H_DIM * 2) + jb;
    const uint32_t bdst = (bg ? 20480 + brow * 80 : 25600 + (brow - 64) * 80) + jb + sbase;

    // fragment address components
    const int arow_l = (lane & 7) + ((lane >> 3) & 1) * 8;
    const uint32_t akb = (lane >> 4) * 16;
    const uint32_t aoff0 = (wm * 32 + arow_l) * 80 + akb;       // mt=0
    const uint32_t boff  = (wn * 32 + lane) * 80;

    float accg[32], accu[32];
#pragma unroll
    for (int i = 0; i < 32; i++) { accg[i] = 0.f; accu[i] = 0.f; }

    const int NC = H_DIM / 32;   // 32
#pragma unroll
    for (int j = 0; j < 4; j++) cp16(adst + j * 16, asrc + j * 16);
    cp16(bdst, bsrc); cp16(bdst + 16, bsrc + 16);
    CP_COMMIT();

    for (int c = 0; c < NC; c++) {
        if (c + 1 < NC) {
            const uint32_t bo = ((c + 1) & 1) * 30720;
            const char* as = asrc + (size_t)(c + 1) * 64;
            const char* bs = bsrc + (size_t)(c + 1) * 64;
#pragma unroll
            for (int j = 0; j < 4; j++) cp16(adst + bo + j * 16, as + j * 16);
            cp16(bdst + bo, bs); cp16(bdst + bo + 16, bs + 16);
            CP_COMMIT();
            asm volatile("cp.async.wait_group 1;" ::: "memory");
        } else {
            asm volatile("cp.async.wait_group 0;" ::: "memory");
        }
        __syncthreads();
        const uint32_t buf = sbase + (c & 1) * 30720;
#pragma unroll
        for (int kk = 0; kk < 2; kk++) {
            const uint32_t ko = kk * 32;
            uint32_t Ah[2][4], Al[2][4];
            ldmx4(Ah[0], buf + aoff0 + ko);
            ldmx4(Ah[1], buf + aoff0 + 16 * 80 + ko);
            ldmx4(Al[0], buf + 10240 + aoff0 + ko);
            ldmx4(Al[1], buf + 10240 + aoff0 + 16 * 80 + ko);
            uint32_t Bg0[4], Bg1[4], Bu0[4], Bu1[4];
            ldmx4(Bg0, buf + 20480 + boff + ko);
            ldmx4(Bg1, buf + 20480 + boff + ko + 16);
            ldmx4(Bu0, buf + 25600 + boff + ko);
            ldmx4(Bu1, buf + 25600 + boff + ko + 16);
#pragma unroll
            for (int mt = 0; mt < 2; mt++)
#pragma unroll
            for (int nt = 0; nt < 4; nt++) {
                float* dg = accg + mt * 16 + nt * 4;
                float* du = accu + mt * 16 + nt * 4;
                mma_f16(dg, Ah[mt], Bg0[nt], Bg1[nt]);
                mma_f16(dg, Al[mt], Bg0[nt], Bg1[nt]);
                mma_f16(du, Ah[mt], Bu0[nt], Bu1[nt]);
                mma_f16(du, Al[mt], Bu0[nt], Bu1[nt]);
            }
        }
        __syncthreads();
    }

    // epilogue: h = silu(g) * u, split fp16 hi/lo, write packed
#pragma unroll
    for (int mt = 0; mt < 2; mt++)
#pragma unroll
    for (int nt = 0; nt < 4; nt++) {
        const int mB   = wm * 32 + mt * 16 + (lane >> 2);
        const int gcol = n0 + wn * 32 + nt * 8 + (lane & 3) * 2;
        const float* dg = accg + mt * 16 + nt * 4;
        const float* du = accu + mt * 16 + nt * 4;
#pragma unroll
        for (int half = 0; half < 2; half++) {
            const int m = mB + half * 8;
            if (m < mcnt) {
                float g0 = dg[half * 2], g1 = dg[half * 2 + 1];
                float u0 = du[half * 2], u1 = du[half * 2 + 1];
                float h0 = g0 / (1.f + __expf(-g0)) * u0;
                float h1 = g1 / (1.f + __expf(-g1)) * u1;
                __half hh0 = __float2half_rn(h0);
                __half hh1 = __float2half_rn(h1);
                float r0 = h0 - __half2float(hh0);
                float r1 = h1 - __half2float(hh1);
                __half2 th = __halves2half2(hh0, hh1);
                size_t o = ((size_t)(row0 + m) * I_DIM + gcol) >> 1;
                g_h_hi[o] = *reinterpret_cast<uint32_t*>(&th);
                g_h_lo[o] = pack_f16(r0, r1);
            }
        }
    }
}

// ---------------- GEMM2: down projection ----------------------------------
// CTA 128x64, K=768 in 24 chunks of 32.
// smem/buffer: A_hi@0, A_lo@10240, B@20480 (5120). Stride 25600, dbuf 51200.
__global__ __launch_bounds__(256) void gemm2_hmma() {
    extern __shared__ char dsm[];
    const int tile = blockIdx.y;
    if (tile >= g_ntiles) return;
    const int e    = g_tile_e[tile];
    const int row0 = g_tile_row[tile];
    const int mcnt = g_tile_m[tile];
    const int n0   = blockIdx.x * 64;
    const int tid  = threadIdx.x, lane = tid & 31, wid = tid >> 5;
    const int wm   = wid & 3, wn = wid >> 2;
    const uint32_t sbase = smem_u32(dsm);

    const int ar = tid & 127, apart = tid >> 7;
    const int arow = row0 + min(ar, mcnt - 1);
    const char* asrc = (const char*)(apart ? g_h_lo : g_h_hi) + (size_t)arow * (I_DIM * 2);
    const uint32_t adst = sbase + apart * 10240 + ar * 80;
    // B: 64 rows x 4 cp16 = 256 jobs, 1 per thread
    const int brow = tid >> 2;
    const uint32_t jb = (tid & 3) * 16;
    const char* bsrc = (const char*)g_wd + (size_t)(e * H_DIM + n0 + brow) * (I_DIM * 2) + jb;
    const uint32_t bdst = sbase + 20480 + brow * 80 + jb;

    const int arow_l = (lane & 7) + ((lane >> 3) & 1) * 8;
    const uint32_t akb = (lane >> 4) * 16;
    const uint32_t aoff0 = (wm * 32 + arow_l) * 80 + akb;
    const uint32_t boff  = (wn * 32 + lane) * 80;

    float acc[32];
#pragma unroll
    for (int i = 0; i < 32; i++) acc[i] = 0.f;

    const int NC = I_DIM / 32;   // 24
#pragma unroll
    for (int j = 0; j < 4; j++) cp16(adst + j * 16, asrc + j * 16);
    cp16(bdst, bsrc);
    CP_COMMIT();

    for (int c = 0; c < NC; c++) {
        if (c + 1 < NC) {
            const uint32_t bo = ((c + 1) & 1) * 25600;
            const char* as = asrc + (size_t)(c + 1) * 64;
#pragma unroll
            for (int j = 0; j < 4; j++) cp16(adst + bo + j * 16, as + j * 16);
            cp16(bdst + bo, bsrc + (size_t)(c + 1) * 64);
            CP_COMMIT();
            asm volatile("cp.async.wait_group 1;" ::: "memory");
        } else {
            asm volatile("cp.async.wait_group 0;" ::: "memory");
        }
        __syncthreads();
        const uint32_t buf = sbase + (c & 1) * 25600;
#pragma unroll
        for (int kk = 0; kk < 2; kk++) {
            const uint32_t ko = kk * 32;
            uint32_t Ah[2][4], Al[2][4];
            ldmx4(Ah[0], buf + aoff0 + ko);
            ldmx4(Ah[1], buf + aoff0 + 16 * 80 + ko);
            ldmx4(Al[0], buf + 10240 + aoff0 + ko);
            ldmx4(Al[1], buf + 10240 + aoff0 + 16 * 80 + ko);
            uint32_t B0[4], B1[4];
            ldmx4(B0, buf + 20480 + boff + ko);
            ldmx4(B1, buf + 20480 + boff + ko + 16);
#pragma unroll
            for (int mt = 0; mt < 2; mt++)
#pragma unroll
            for (int nt = 0; nt < 4; nt++) {
                float* d = acc + mt * 16 + nt * 4;
                mma_f16(d, Ah[mt], B0[nt], B1[nt]);
                mma_f16(d, Al[mt], B0[nt], B1[nt]);
            }
        }
        __syncthreads();
    }

#pragma unroll
    for (int mt = 0; mt < 2; mt++)
#pragma unroll
    for (int nt = 0; nt < 4; nt++) {
        const int mB   = wm * 32 + mt * 16 + (lane >> 2);
        const int gcol = n0 + wn * 32 + nt * 8 + (lane & 3) * 2;
        const float* d = acc + mt * 16 + nt * 4;
#pragma unroll
        for (int half = 0; half < 2; half++) {
            const int m = mB + half * 8;
            if (m < mcnt) {
                *(float2*)(g_y + (size_t)(row0 + m) * H_DIM + gcol) =
                    make_float2(d[half * 2], d[half * 2 + 1]);
            }
        }
    }
}

// ---------------- combine -------------------------------------------------
__global__ void combine_kernel(const float* __restrict__ rw, float4* __restrict__ out)
{
    int idx = blockIdx.x * blockDim.x + threadIdx.x;
    int t = idx >> 8;
    int c = idx & 255;
    float w0 = rw[2 * t];
    float w1 = rw[2 * t + 1];
    int p0 = g_slotpos[2 * t];
    int p1 = g_slotpos[2 * t + 1];
    const float4* y = (const float4*)g_y;
    float4 y0 = y[(size_t)p0 * 256 + c];
    float4 y1 = y[(size_t)p1 * 256 + c];
    out[idx] = make_float4(w0 * y0.x + w1 * y1.x,
                           w0 * y0.y + w1 * y1.y,
                           w0 * y0.z + w1 * y1.z,
                           w0 * y0.w + w1 * y1.w);
}

// ---------------- launch ---------------------------------------------------
extern "C" void kernel_launch(void* const* d_in, const int* in_sizes, int n_in,
                              void* d_out, int out_size)
{
    const float* x   = (const float*)d_in[0];
    const float* rw  = (const float*)d_in[1];
    const void*  se  = d_in[2];
    const float* Wg  = (const float*)d_in[3];
    const float* Wu  = (const float*)d_in[4];
    const float* Wd  = (const float*)d_in[5];
    float*       out = (float*)d_out;

    const int SM1 = 2 * 30720;   // 61440
    const int SM2 = 2 * 25600;   // 51200
    cudaFuncSetAttribute(gemm1_hmma, cudaFuncAttributeMaxDynamicSharedMemorySize, SM1);
    cudaFuncSetAttribute(gemm2_hmma, cudaFuncAttributeMaxDynamicSharedMemorySize, SM2);

    detect_kernel<<<1, 256>>>((const long long*)se);
    route_kernel<<<1, 256>>>(se);

    const int xn4 = T_TOK * H_DIM / 4;   // 1048576
    const int wn4 = WELEM / 4;           // 1572864
    split_x<<<xn4 / 256, 256>>>((const float4*)x, xn4);
    cvt_w<<<wn4 / 256, 256>>>((const float4*)Wg, 1, wn4);
    cvt_w<<<wn4 / 256, 256>>>((const float4*)Wu, 2, wn4);
    cvt_w<<<wn4 / 256, 256>>>((const float4*)Wd, 3, wn4);

    gemm1_hmma<<<dim3(I_DIM / 64, MAX_TILES), 256, SM1>>>();
    gemm2_hmma<<<dim3(H_DIM / 64, MAX_TILES), 256, SM2>>>();
    combine_kernel<<<(T_TOK * H_DIM / 4) / 256, 256>>>(rw, (float4*)out);
    (void)in_sizes; (void)n_in; (void)out_size;
}

// round 6
// speedup vs baseline: 3.0098x; 1.6972x over previous
#include <cuda_runtime.h>
#include <cuda_fp16.h>
#include <cstdint>
#include <math.h>

// Problem constants
#define B_BATCH 4
#define S_SEQ   1024
#define H_DIM   1024
#define I_DIM   768
#define E_NUM   8
#define T_TOK   4096
#define TKS     8192

#define BM        128
#define MAX_TILES 72
#define WELEM     (E_NUM * I_DIM * H_DIM)     // 6291456

// ---------------- device scratch (fp16 packed as uint32 pairs) -----------
__device__ int      g_ntiles;
__device__ int      g_tile_e[MAX_TILES];
__device__ int      g_tile_row[MAX_TILES];
__device__ int      g_tile_m[MAX_TILES];
__device__ int      g_tok[TKS];
__device__ int      g_slotpos[TKS];
__device__ uint32_t g_x16[T_TOK * H_DIM / 2];        // fp16x2
__device__ uint32_t g_wg[WELEM / 2];
__device__ uint32_t g_wu[WELEM / 2];
__device__ uint32_t g_wd[WELEM / 2];
__device__ uint32_t g_h16[(size_t)TKS * I_DIM / 2];
__device__ float    g_y[(size_t)TKS * H_DIM];

// ---------------- helpers ----------------
__device__ __forceinline__ uint32_t smem_u32(const void* p) {
    uint32_t r;
    asm("{ .reg .u64 t; cvta.to.shared.u64 t, %1; cvt.u32.u64 %0, t; }"
        : "=r"(r) : "l"(p));
    return r;
}
__device__ __forceinline__ void cp16(uint32_t dst, const void* src) {
    asm volatile("cp.async.cg.shared.global [%0], [%1], 16;"
                 :: "r"(dst), "l"(__cvta_generic_to_global(src)) : "memory");
}
#define CP_COMMIT() asm volatile("cp.async.commit_group;" ::: "memory")

__device__ __forceinline__ void ldmx4(uint32_t* r, uint32_t a) {
    asm volatile("ldmatrix.sync.aligned.m8n8.x4.shared.b16 {%0,%1,%2,%3}, [%4];"
                 : "=r"(r[0]), "=r"(r[1]), "=r"(r[2]), "=r"(r[3]) : "r"(a));
}
__device__ __forceinline__ void mma_f16(float* d, const uint32_t* a,
                                        uint32_t b0, uint32_t b1) {
    asm volatile(
        "mma.sync.aligned.m16n8k16.row.col.f32.f16.f16.f32 "
        "{%0,%1,%2,%3}, {%4,%5,%6,%7}, {%8,%9}, {%0,%1,%2,%3};"
        : "+f"(d[0]), "+f"(d[1]), "+f"(d[2]), "+f"(d[3])
        : "r"(a[0]), "r"(a[1]), "r"(a[2]), "r"(a[3]), "r"(b0), "r"(b1));
}
__device__ __forceinline__ uint32_t pack_f16(float a, float b) {
    __half2 t = __floats2half2_rn(a, b);
    return *reinterpret_cast<uint32_t*>(&t);
}

// ---------------- routing (detect merged in) ----------------
__global__ void route_kernel(const void* __restrict__ se_raw) {
    __shared__ int s_cnt[E_NUM];
    __shared__ int s_pos[E_NUM];
    __shared__ int s_bad;
    int tid = threadIdx.x;
    if (tid == 0) s_bad = 0;
    if (tid < E_NUM) s_cnt[tid] = 0;
    __syncthreads();
    const long long* se64 = (const long long*)se_raw;
    const int*       se32 = (const int*)se_raw;
    int bad = 0;
    for (int i = tid; i < 2048; i += blockDim.x) {
        long long v = se64[i];
        if (v < 0 || v >= E_NUM) bad = 1;
    }
    if (bad) atomicOr(&s_bad, 1);
    __syncthreads();
    const int is64 = s_bad ? 0 : 1;
    for (int s = tid; s < TKS; s += blockDim.x) {
        int e = is64 ? (int)se64[s] : se32[s];
        atomicAdd(&s_cnt[e], 1);
    }
    __syncthreads();
    if (tid == 0) {
        int off = 0, nt = 0;
        for (int e = 0; e < E_NUM; e++) {
            int c = s_cnt[e];
            s_pos[e] = off;
            for (int r = 0; r < c; r += BM) {
                g_tile_e[nt]   = e;
                g_tile_row[nt] = off + r;
                g_tile_m[nt]   = min(BM, c - r);
                nt++;
            }
            off += c;
        }
        g_ntiles = nt;
    }
    __syncthreads();
    for (int s = tid; s < TKS; s += blockDim.x) {
        int e = is64 ? (int)se64[s] : se32[s];
        int pos = atomicAdd(&s_pos[e], 1);
        g_tok[pos]   = s >> 1;
        g_slotpos[s] = pos;
    }
}

// ---------------- prep: fp32 -> fp16 ----------------
__global__ void cvt_f16(const float4* __restrict__ src, int which, int n4) {
    uint2* dst = (which == 0) ? (uint2*)g_x16 : (which == 1) ? (uint2*)g_wg
               : (which == 2) ? (uint2*)g_wu  : (uint2*)g_wd;
    int i = blockIdx.x * blockDim.x + threadIdx.x;
    if (i >= n4) return;
    float4 v = src[i];
    dst[i] = make_uint2(pack_f16(v.x, v.y), pack_f16(v.z, v.w));
}

// ---------------- GEMM1: gate+up fused, SiLU epilogue --------------------
// CTA 128x64, K=1024, 32 chunks of K=32. 4-stage cp.async pipeline,
// one __syncthreads per chunk. Stage layout (pitch 80B, 64B data):
//   A rows 0-127 @ 0, gate rows 0-63 @ 10240, up rows 0-63 @ 15360.
// Stage stride 20480, 4 stages = 81920 B.
#define ST1 20480
__global__ __launch_bounds__(256) void gemm1_hmma() {
    extern __shared__ char dsm[];
    const int tile = blockIdx.y;
    if (tile >= g_ntiles) return;
    const int e    = g_tile_e[tile];
    const int row0 = g_tile_row[tile];
    const int mcnt = g_tile_m[tile];
    const int n0   = blockIdx.x * 64;
    const int tid  = threadIdx.x, lane = tid & 31, wid = tid >> 5;
    const int wm   = wid & 3, wn = wid >> 2;
    const uint32_t sbase = smem_u32(dsm);

    // copy role: threads 0-127 -> A row tid; 128-255 -> B row tid-128
    const int crow = tid & 127;
    const char* csrc;
    uint32_t cdst;
    if (tid < 128) {
        int tokA = g_tok[row0 + min(crow, mcnt - 1)];
        csrc = (const char*)g_x16 + (size_t)tokA * (H_DIM * 2);
        cdst = sbase + crow * 80;
    } else {
        const bool gate = crow < 64;
        const uint32_t* w = gate ? g_wg : g_wu;
        const int r = gate ? crow : crow - 64;
        csrc = (const char*)w + (size_t)(e * I_DIM + n0 + r) * (H_DIM * 2);
        cdst = sbase + 10240 + crow * 80;
    }

    const int arow_l = (lane & 7) + ((lane >> 3) & 1) * 8;
    const uint32_t akb  = (lane >> 4) * 16;
    const uint32_t aoff = (wm * 32 + arow_l) * 80 + akb;
    const uint32_t bgoff = 10240 + (wn * 32 + lane) * 80;
    const uint32_t buoff = 15360 + (wn * 32 + lane) * 80;

    float accg[32], accu[32];
#pragma unroll
    for (int i = 0; i < 32; i++) { accg[i] = 0.f; accu[i] = 0.f; }

    const int NC = H_DIM / 32;   // 32
#pragma unroll
    for (int s = 0; s < 3; s++) {
        const uint32_t d = cdst + s * ST1;
        const char* sc = csrc + s * 64;
#pragma unroll
        for (int j = 0; j < 4; j++) cp16(d + j * 16, sc + j * 16);
        CP_COMMIT();
    }

    for (int c = 0; c < NC; c++) {
        asm volatile("cp.async.wait_group 2;" ::: "memory");
        __syncthreads();
        const uint32_t buf = sbase + (c & 3) * ST1;
#pragma unroll
        for (int kk = 0; kk < 2; kk++) {
            const uint32_t ko = kk * 32;
            uint32_t Ah[2][4];
            ldmx4(Ah[0], buf + aoff + ko);
            ldmx4(Ah[1], buf + aoff + 16 * 80 + ko);
            uint32_t Bg0[4], Bg1[4], Bu0[4], Bu1[4];
            ldmx4(Bg0, buf + bgoff + ko);
            ldmx4(Bg1, buf + bgoff + ko + 16);
            ldmx4(Bu0, buf + buoff + ko);
            ldmx4(Bu1, buf + buoff + ko + 16);
#pragma unroll
            for (int mt = 0; mt < 2; mt++)
#pragma unroll
            for (int nt = 0; nt < 4; nt++) {
                mma_f16(accg + mt * 16 + nt * 4, Ah[mt], Bg0[nt], Bg1[nt]);
                mma_f16(accu + mt * 16 + nt * 4, Ah[mt], Bu0[nt], Bu1[nt]);
            }
        }
        if (c + 3 < NC) {
            const uint32_t d = cdst + ((c + 3) & 3) * ST1;
            const char* sc = csrc + (size_t)(c + 3) * 64;
#pragma unroll
            for (int j = 0; j < 4; j++) cp16(d + j * 16, sc + j * 16);
        }
        CP_COMMIT();
    }

    // epilogue: h = silu(g) * u -> fp16
#pragma unroll
    for (int mt = 0; mt < 2; mt++)
#pragma unroll
    for (int nt = 0; nt < 4; nt++) {
        const int mB   = wm * 32 + mt * 16 + (lane >> 2);
        const int gcol = n0 + wn * 32 + nt * 8 + (lane & 3) * 2;
        const float* dg = accg + mt * 16 + nt * 4;
        const float* du = accu + mt * 16 + nt * 4;
#pragma unroll
        for (int half = 0; half < 2; half++) {
            const int m = mB + half * 8;
            if (m < mcnt) {
                float g0 = dg[half * 2], g1 = dg[half * 2 + 1];
                float u0 = du[half * 2], u1 = du[half * 2 + 1];
                float h0 = g0 / (1.f + __expf(-g0)) * u0;
                float h1 = g1 / (1.f + __expf(-g1)) * u1;
                g_h16[((size_t)(row0 + m) * I_DIM + gcol) >> 1] = pack_f16(h0, h1);
            }
        }
    }
}

// ---------------- GEMM2: down projection ----------------------------------
// CTA 128x64, K=768, 24 chunks of 32. Stage: A @0 (10240), B @10240 (5120).
// Stage stride 15360, 4 stages = 61440 B.
#define ST2 15360
__global__ __launch_bounds__(256) void gemm2_hmma() {
    extern __shared__ char dsm[];
    const int tile = blockIdx.y;
    if (tile >= g_ntiles) return;
    const int e    = g_tile_e[tile];
    const int row0 = g_tile_row[tile];
    const int mcnt = g_tile_m[tile];
    const int n0   = blockIdx.x * 64;
    const int tid  = threadIdx.x, lane = tid & 31, wid = tid >> 5;
    const int wm   = wid & 3, wn = wid >> 2;
    const uint32_t sbase = smem_u32(dsm);

    // copy roles: threads 0-127 -> A row (4 quads); 128-255 -> B halfrow (2 quads)
    const char* csrc;
    uint32_t cdst;
    int nq;
    if (tid < 128) {
        int arow = row0 + min(tid, mcnt - 1);
        csrc = (const char*)g_h16 + (size_t)arow * (I_DIM * 2);
        cdst = sbase + tid * 80;
        nq = 4;
    } else {
        const int r = (tid - 128) >> 1;
        const uint32_t hb = (tid & 1) * 32;
        csrc = (const char*)g_wd + (size_t)(e * H_DIM + n0 + r) * (I_DIM * 2) + hb;
        cdst = sbase + 10240 + r * 80 + hb;
        nq = 2;
    }

    const int arow_l = (lane & 7) + ((lane >> 3) & 1) * 8;
    const uint32_t akb  = (lane >> 4) * 16;
    const uint32_t aoff = (wm * 32 + arow_l) * 80 + akb;
    const uint32_t boff = 10240 + (wn * 32 + lane) * 80;

    float acc[32];
#pragma unroll
    for (int i = 0; i < 32; i++) acc[i] = 0.f;

    const int NC = I_DIM / 32;   // 24
#pragma unroll
    for (int s = 0; s < 3; s++) {
        const uint32_t d = cdst + s * ST2;
        const char* sc = csrc + s * 64;
        for (int j = 0; j < nq; j++) cp16(d + j * 16, sc + j * 16);
        CP_COMMIT();
    }

    for (int c = 0; c < NC; c++) {
        asm volatile("cp.async.wait_group 2;" ::: "memory");
        __syncthreads();
        const uint32_t buf = sbase + (c & 3) * ST2;
#pragma unroll
        for (int kk = 0; kk < 2; kk++) {
            const uint32_t ko = kk * 32;
            uint32_t Ah[2][4];
            ldmx4(Ah[0], buf + aoff + ko);
            ldmx4(Ah[1], buf + aoff + 16 * 80 + ko);
            uint32_t B0[4], B1[4];
            ldmx4(B0, buf + boff + ko);
            ldmx4(B1, buf + boff + ko + 16);
#pragma unroll
            for (int mt = 0; mt < 2; mt++)
#pragma unroll
            for (int nt = 0; nt < 4; nt++)
                mma_f16(acc + mt * 16 + nt * 4, Ah[mt], B0[nt], B1[nt]);
        }
        if (c + 3 < NC) {
            const uint32_t d = cdst + ((c + 3) & 3) * ST2;
            const char* sc = csrc + (size_t)(c + 3) * 64;
            for (int j = 0; j < nq; j++) cp16(d + j * 16, sc + j * 16);
        }
        CP_COMMIT();
    }

#pragma unroll
    for (int mt = 0; mt < 2; mt++)
#pragma unroll
    for (int nt = 0; nt < 4; nt++) {
        const int mB   = wm * 32 + mt * 16 + (lane >> 2);
        const int gcol = n0 + wn * 32 + nt * 8 + (lane & 3) * 2;
        const float* d = acc + mt * 16 + nt * 4;
#pragma unroll
        for (int half = 0; half < 2; half++) {
            const int m = mB + half * 8;
            if (m < mcnt) {
                *(float2*)(g_y + (size_t)(row0 + m) * H_DIM + gcol) =
                    make_float2(d[half * 2], d[half * 2 + 1]);
            }
        }
    }
}

// ---------------- combine -------------------------------------------------
__global__ void combine_kernel(const float* __restrict__ rw, float4* __restrict__ out)
{
    int idx = blockIdx.x * blockDim.x + threadIdx.x;
    int t = idx >> 8;
    int c = idx & 255;
    float w0 = rw[2 * t];
    float w1 = rw[2 * t + 1];
    int p0 = g_slotpos[2 * t];
    int p1 = g_slotpos[2 * t + 1];
    const float4* y = (const float4*)g_y;
    float4 y0 = y[(size_t)p0 * 256 + c];
    float4 y1 = y[(size_t)p1 * 256 + c];
    out[idx] = make_float4(w0 * y0.x + w1 * y1.x,
                           w0 * y0.y + w1 * y1.y,
                           w0 * y0.z + w1 * y1.z,
                           w0 * y0.w + w1 * y1.w);
}

// ---------------- launch ---------------------------------------------------
extern "C" void kernel_launch(void* const* d_in, const int* in_sizes, int n_in,
                              void* d_out, int out_size)
{
    const float* x   = (const float*)d_in[0];
    const float* rw  = (const float*)d_in[1];
    const void*  se  = d_in[2];
    const float* Wg  = (const float*)d_in[3];
    const float* Wu  = (const float*)d_in[4];
    const float* Wd  = (const float*)d_in[5];
    float*       out = (float*)d_out;

    const int SM1 = 4 * ST1;   // 81920
    const int SM2 = 4 * ST2;   // 61440
    cudaFuncSetAttribute(gemm1_hmma, cudaFuncAttributeMaxDynamicSharedMemorySize, SM1);
    cudaFuncSetAttribute(gemm2_hmma, cudaFuncAttributeMaxDynamicSharedMemorySize, SM2);

    const int xn4 = T_TOK * H_DIM / 4;   // 1048576
    const int wn4 = WELEM / 4;           // 1572864

    // launch order matters for ncu (-s 5 -c 1 captures launch #6 = gemm1)
    route_kernel<<<1, 256>>>(se);
    cvt_f16<<<xn4 / 256, 256>>>((const float4*)x, 0, xn4);
    cvt_f16<<<wn4 / 256, 256>>>((const float4*)Wg, 1, wn4);
    cvt_f16<<<wn4 / 256, 256>>>((const float4*)Wu, 2, wn4);
    cvt_f16<<<wn4 / 256, 256>>>((const float4*)Wd, 3, wn4);
    gemm1_hmma<<<dim3(I_DIM / 64, MAX_TILES), 256, SM1>>>();
    gemm2_hmma<<<dim3(H_DIM / 64, MAX_TILES), 256, SM2>>>();
    combine_kernel<<<(T_TOK * H_DIM / 4) / 256, 256>>>(rw, (float4*)out);
    (void)in_sizes; (void)n_in; (void)out_size;
}

// round 7
// speedup vs baseline: 3.2779x; 1.0891x over previous
#include <cuda_runtime.h>
#include <cuda_fp16.h>
#include <cstdint>
#include <math.h>

// Problem constants
#define B_BATCH 4
#define S_SEQ   1024
#define H_DIM   1024
#define I_DIM   768
#define E_NUM   8
#define T_TOK   4096
#define TKS     8192

#define BM        128
#define MAX_TILES 72
#define WELEM     (E_NUM * I_DIM * H_DIM)     // 6291456
#define XN4       (T_TOK * H_DIM / 4)         // 1048576
#define WN4       (WELEM / 4)                 // 1572864

// ---------------- device scratch (fp16 packed as uint32 pairs) -----------
__device__ int      g_ntiles;
__device__ int      g_tile_e[MAX_TILES];
__device__ int      g_tile_row[MAX_TILES];
__device__ int      g_tile_m[MAX_TILES];
__device__ int      g_tok[TKS];
__device__ int      g_slotpos[TKS];
__device__ uint32_t g_x16[T_TOK * H_DIM / 2];        // fp16x2
__device__ uint32_t g_wg[WELEM / 2];
__device__ uint32_t g_wu[WELEM / 2];
__device__ uint32_t g_wd[WELEM / 2];
__device__ uint32_t g_h16[(size_t)TKS * I_DIM / 2];
__device__ float    g_y[(size_t)TKS * H_DIM];

// ---------------- helpers ----------------
__device__ __forceinline__ uint32_t smem_u32(const void* p) {
    uint32_t r;
    asm("{ .reg .u64 t; cvta.to.shared.u64 t, %1; cvt.u32.u64 %0, t; }"
        : "=r"(r) : "l"(p));
    return r;
}
__device__ __forceinline__ void cp16(uint32_t dst, const void* src) {
    asm volatile("cp.async.cg.shared.global [%0], [%1], 16;"
                 :: "r"(dst), "l"(__cvta_generic_to_global(src)) : "memory");
}
#define CP_COMMIT() asm volatile("cp.async.commit_group;" ::: "memory")

__device__ __forceinline__ void ldmx4(uint32_t* r, uint32_t a) {
    asm volatile("ldmatrix.sync.aligned.m8n8.x4.shared.b16 {%0,%1,%2,%3}, [%4];"
                 : "=r"(r[0]), "=r"(r[1]), "=r"(r[2]), "=r"(r[3]) : "r"(a));
}
__device__ __forceinline__ void mma_f16(float* d, const uint32_t* a,
                                        uint32_t b0, uint32_t b1) {
    asm volatile(
        "mma.sync.aligned.m16n8k16.row.col.f32.f16.f16.f32 "
        "{%0,%1,%2,%3}, {%4,%5,%6,%7}, {%8,%9}, {%0,%1,%2,%3};"
        : "+f"(d[0]), "+f"(d[1]), "+f"(d[2]), "+f"(d[3])
        : "r"(a[0]), "r"(a[1]), "r"(a[2]), "r"(a[3]), "r"(b0), "r"(b1));
}
__device__ __forceinline__ uint32_t pack_f16(float a, float b) {
    __half2 t = __floats2half2_rn(a, b);
    return *reinterpret_cast<uint32_t*>(&t);
}

// ---------------- routing (dtype detect merged) ----------------
__global__ void route_kernel(const void* __restrict__ se_raw) {
    __shared__ int s_cnt[E_NUM];
    __shared__ int s_pos[E_NUM];
    __shared__ int s_bad;
    int tid = threadIdx.x;
    if (tid == 0) s_bad = 0;
    if (tid < E_NUM) s_cnt[tid] = 0;
    __syncthreads();
    const long long* se64 = (const long long*)se_raw;
    const int*       se32 = (const int*)se_raw;
    int bad = 0;
    for (int i = tid; i < 2048; i += blockDim.x) {
        long long v = se64[i];
        if (v < 0 || v >= E_NUM) bad = 1;
    }
    if (bad) atomicOr(&s_bad, 1);
    __syncthreads();
    const int is64 = s_bad ? 0 : 1;
    for (int s = tid; s < TKS; s += blockDim.x) {
        int e = is64 ? (int)se64[s] : se32[s];
        atomicAdd(&s_cnt[e], 1);
    }
    __syncthreads();
    if (tid == 0) {
        int off = 0, nt = 0;
        for (int e = 0; e < E_NUM; e++) {
            int c = s_cnt[e];
            s_pos[e] = off;
            for (int r = 0; r < c; r += BM) {
                g_tile_e[nt]   = e;
                g_tile_row[nt] = off + r;
                g_tile_m[nt]   = min(BM, c - r);
                nt++;
            }
            off += c;
        }
        g_ntiles = nt;
    }
    __syncthreads();
    for (int s = tid; s < TKS; s += blockDim.x) {
        int e = is64 ? (int)se64[s] : se32[s];
        int pos = atomicAdd(&s_pos[e], 1);
        g_tok[pos]   = s >> 1;
        g_slotpos[s] = pos;
    }
}

// ---------------- prep: all fp32 -> fp16 in one kernel ----------------
__global__ void cvt_all(const float4* __restrict__ x,  const float4* __restrict__ wg,
                        const float4* __restrict__ wu, const float4* __restrict__ wd) {
    int i = blockIdx.x * blockDim.x + threadIdx.x;
    const float4* src;
    uint2* dst;
    if (i < XN4)                      { src = x;  dst = (uint2*)g_x16; }
    else if ((i -= XN4) < WN4)        { src = wg; dst = (uint2*)g_wg;  }
    else if ((i -= WN4) < WN4)        { src = wu; dst = (uint2*)g_wu;  }
    else if ((i -= WN4) < WN4)        { src = wd; dst = (uint2*)g_wd;  }
    else return;
    float4 v = src[i];
    dst[i] = make_uint2(pack_f16(v.x, v.y), pack_f16(v.z, v.w));
}

// ---------------- GEMM1: gate+up fused, SiLU epilogue --------------------
// CTA 128x64 (x2 matrices), K=1024 in 16 chunks of K=64 (128B/row, 144B pitch).
// Stage: A rows 0-127 @0 (18432), Bg @18432 (9216), Bu @27648 (9216).
// Stage stride 36864, 3 stages = 110592 B. 2 CTAs/SM.
#define ST1 36864
__global__ __launch_bounds__(256, 2) void gemm1_hmma() {
    extern __shared__ char dsm[];
    const int tile = blockIdx.y;
    if (tile >= g_ntiles) return;
    const int e    = g_tile_e[tile];
    const int row0 = g_tile_row[tile];
    const int mcnt = g_tile_m[tile];
    const int n0   = blockIdx.x * 64;
    const int tid  = threadIdx.x, lane = tid & 31, wid = tid >> 5;
    const int wm   = wid & 3, wn = wid >> 2;
    const uint32_t sbase = smem_u32(dsm);

    // copy roles: threads 0-127 -> A row tid (8 quads);
    //             128-255 -> B row (0-63 gate, 64-127 up), 8 quads
    const int crow = tid & 127;
    const char* csrc;
    uint32_t cdst;
    if (tid < 128) {
        int tokA = g_tok[row0 + min(crow, mcnt - 1)];
        csrc = (const char*)g_x16 + (size_t)tokA * (H_DIM * 2);
        cdst = sbase + crow * 144;
    } else {
        const bool gate = crow < 64;
        const uint32_t* w = gate ? g_wg : g_wu;
        const int r = gate ? crow : crow - 64;
        csrc = (const char*)w + (size_t)(e * I_DIM + n0 + r) * (H_DIM * 2);
        cdst = sbase + (gate ? 18432 : 27648) + (gate ? crow : crow - 64) * 144;
    }

    const int arow_l = (lane & 7) + ((lane >> 3) & 1) * 8;
    const uint32_t akb   = (lane >> 4) * 16;
    const uint32_t aoff  = (wm * 32 + arow_l) * 144 + akb;
    const uint32_t bgoff = 18432 + (wn * 32 + lane) * 144;
    const uint32_t buoff = 27648 + (wn * 32 + lane) * 144;

    float accg[32], accu[32];
#pragma unroll
    for (int i = 0; i < 32; i++) { accg[i] = 0.f; accu[i] = 0.f; }

    const int NC = H_DIM / 64;   // 16
#pragma unroll
    for (int s = 0; s < 2; s++) {
        const uint32_t d = cdst + s * ST1;
        const char* sc = csrc + s * 128;
#pragma unroll
        for (int j = 0; j < 8; j++) cp16(d + j * 16, sc + j * 16);
        CP_COMMIT();
    }

    for (int c = 0; c < NC; c++) {
        asm volatile("cp.async.wait_group 1;" ::: "memory");
        __syncthreads();
        const uint32_t buf = sbase + (c % 3) * ST1;
#pragma unroll
        for (int kk = 0; kk < 4; kk++) {
            const uint32_t ko = kk * 32;
            uint32_t Ah[2][4];
            ldmx4(Ah[0], buf + aoff + ko);
            ldmx4(Ah[1], buf + aoff + 16 * 144 + ko);
            uint32_t Bg0[4], Bg1[4], Bu0[4], Bu1[4];
            ldmx4(Bg0, buf + bgoff + ko);
            ldmx4(Bg1, buf + bgoff + ko + 16);
            ldmx4(Bu0, buf + buoff + ko);
            ldmx4(Bu1, buf + buoff + ko + 16);
#pragma unroll
            for (int mt = 0; mt < 2; mt++)
#pragma unroll
            for (int nt = 0; nt < 4; nt++) {
                mma_f16(accg + mt * 16 + nt * 4, Ah[mt], Bg0[nt], Bg1[nt]);
                mma_f16(accu + mt * 16 + nt * 4, Ah[mt], Bu0[nt], Bu1[nt]);
            }
        }
        if (c + 2 < NC) {
            const uint32_t d = cdst + ((c + 2) % 3) * ST1;
            const char* sc = csrc + (size_t)(c + 2) * 128;
#pragma unroll
            for (int j = 0; j < 8; j++) cp16(d + j * 16, sc + j * 16);
        }
        CP_COMMIT();
    }

    // epilogue: h = silu(g) * u -> fp16
#pragma unroll
    for (int mt = 0; mt < 2; mt++)
#pragma unroll
    for (int nt = 0; nt < 4; nt++) {
        const int mB   = wm * 32 + mt * 16 + (lane >> 2);
        const int gcol = n0 + wn * 32 + nt * 8 + (lane & 3) * 2;
        const float* dg = accg + mt * 16 + nt * 4;
        const float* du = accu + mt * 16 + nt * 4;
#pragma unroll
        for (int half = 0; half < 2; half++) {
            const int m = mB + half * 8;
            if (m < mcnt) {
                float g0 = dg[half * 2], g1 = dg[half * 2 + 1];
                float u0 = du[half * 2], u1 = du[half * 2 + 1];
                float h0 = g0 / (1.f + __expf(-g0)) * u0;
                float h1 = g1 / (1.f + __expf(-g1)) * u1;
                g_h16[((size_t)(row0 + m) * I_DIM + gcol) >> 1] = pack_f16(h0, h1);
            }
        }
    }
}

// ---------------- GEMM2: down projection ----------------------------------
// CTA 128x128 (warp 32x64, 4m x 2n), K=768 in 24 chunks of 32 (80B pitch).
// Stage: A rows 0-127 @0 (10240), B rows 0-127 @10240 (10240).
// Stage stride 20480, 4 stages = 81920 B. 2 CTAs/SM.
#define ST2 20480
__global__ __launch_bounds__(256, 2) void gemm2_hmma() {
    extern __shared__ char dsm[];
    const int tile = blockIdx.y;
    if (tile >= g_ntiles) return;
    const int e    = g_tile_e[tile];
    const int row0 = g_tile_row[tile];
    const int mcnt = g_tile_m[tile];
    const int n0   = blockIdx.x * 128;
    const int tid  = threadIdx.x, lane = tid & 31, wid = tid >> 5;
    const int wm   = wid & 3, wn = wid >> 2;   // wn in {0,1}
    const uint32_t sbase = smem_u32(dsm);

    // copy roles: threads 0-127 -> A row tid (4 quads); 128-255 -> B row (4 quads)
    const int crow = tid & 127;
    const char* csrc;
    uint32_t cdst;
    if (tid < 128) {
        int arow = row0 + min(crow, mcnt - 1);
        csrc = (const char*)g_h16 + (size_t)arow * (I_DIM * 2);
        cdst = sbase + crow * 80;
    } else {
        csrc = (const char*)g_wd + (size_t)(e * H_DIM + n0 + crow) * (I_DIM * 2);
        cdst = sbase + 10240 + crow * 80;
    }

    const int arow_l = (lane & 7) + ((lane >> 3) & 1) * 8;
    const uint32_t akb   = (lane >> 4) * 16;
    const uint32_t aoff  = (wm * 32 + arow_l) * 80 + akb;
    const uint32_t boffa = 10240 + (wn * 64 + lane) * 80;
    const uint32_t boffb = 10240 + (wn * 64 + 32 + lane) * 80;

    float acc[64];
#pragma unroll
    for (int i = 0; i < 64; i++) acc[i] = 0.f;

    const int NC = I_DIM / 32;   // 24
#pragma unroll
    for (int s = 0; s < 3; s++) {
        const uint32_t d = cdst + s * ST2;
        const char* sc = csrc + s * 64;
#pragma unroll
        for (int j = 0; j < 4; j++) cp16(d + j * 16, sc + j * 16);
        CP_COMMIT();
    }

    for (int c = 0; c < NC; c++) {
        asm volatile("cp.async.wait_group 2;" ::: "memory");
        __syncthreads();
        const uint32_t buf = sbase + (c & 3) * ST2;
#pragma unroll
        for (int kk = 0; kk < 2; kk++) {
            const uint32_t ko = kk * 32;
            uint32_t Ah[2][4];
            ldmx4(Ah[0], buf + aoff + ko);
            ldmx4(Ah[1], buf + aoff + 16 * 80 + ko);
            uint32_t Ba0[4], Ba1[4], Bb0[4], Bb1[4];
            ldmx4(Ba0, buf + boffa + ko);
            ldmx4(Ba1, buf + boffa + ko + 16);
            ldmx4(Bb0, buf + boffb + ko);
            ldmx4(Bb1, buf + boffb + ko + 16);
#pragma unroll
            for (int mt = 0; mt < 2; mt++) {
#pragma unroll
                for (int nt = 0; nt < 4; nt++)
                    mma_f16(acc + mt * 32 + nt * 4, Ah[mt], Ba0[nt], Ba1[nt]);
#pragma unroll
                for (int nt = 0; nt < 4; nt++)
                    mma_f16(acc + mt * 32 + 16 + nt * 4, Ah[mt], Bb0[nt], Bb1[nt]);
            }
        }
        if (c + 3 < NC) {
            const uint32_t d = cdst + ((c + 3) & 3) * ST2;
            const char* sc = csrc + (size_t)(c + 3) * 64;
#pragma unroll
            for (int j = 0; j < 4; j++) cp16(d + j * 16, sc + j * 16);
        }
        CP_COMMIT();
    }

#pragma unroll
    for (int mt = 0; mt < 2; mt++)
#pragma unroll
    for (int nt = 0; nt < 8; nt++) {
        const int mB   = wm * 32 + mt * 16 + (lane >> 2);
        const int gcol = n0 + wn * 64 + nt * 8 + (lane & 3) * 2;
        const float* d = acc + mt * 32 + nt * 4;
#pragma unroll
        for (int half = 0; half < 2; half++) {
            const int m = mB + half * 8;
            if (m < mcnt) {
                *(float2*)(g_y + (size_t)(row0 + m) * H_DIM + gcol) =
                    make_float2(d[half * 2], d[half * 2 + 1]);
            }
        }
    }
}

// ---------------- combine -------------------------------------------------
__global__ void combine_kernel(const float* __restrict__ rw, float4* __restrict__ out)
{
    int idx = blockIdx.x * blockDim.x + threadIdx.x;
    int t = idx >> 8;
    int c = idx & 255;
    float w0 = rw[2 * t];
    float w1 = rw[2 * t + 1];
    int p0 = g_slotpos[2 * t];
    int p1 = g_slotpos[2 * t + 1];
    const float4* y = (const float4*)g_y;
    float4 y0 = y[(size_t)p0 * 256 + c];
    float4 y1 = y[(size_t)p1 * 256 + c];
    out[idx] = make_float4(w0 * y0.x + w1 * y1.x,
                           w0 * y0.y + w1 * y1.y,
                           w0 * y0.z + w1 * y1.z,
                           w0 * y0.w + w1 * y1.w);
}

// ---------------- launch ---------------------------------------------------
extern "C" void kernel_launch(void* const* d_in, const int* in_sizes, int n_in,
                              void* d_out, int out_size)
{
    const float* x   = (const float*)d_in[0];
    const float* rw  = (const float*)d_in[1];
    const void*  se  = d_in[2];
    const float* Wg  = (const float*)d_in[3];
    const float* Wu  = (const float*)d_in[4];
    const float* Wd  = (const float*)d_in[5];
    float*       out = (float*)d_out;

    const int SM1 = 3 * ST1;   // 110592
    const int SM2 = 4 * ST2;   // 81920
    cudaFuncSetAttribute(gemm1_hmma, cudaFuncAttributeMaxDynamicSharedMemorySize, SM1);
    cudaFuncSetAttribute(gemm2_hmma, cudaFuncAttributeMaxDynamicSharedMemorySize, SM2);

    route_kernel<<<1, 256>>>(se);
    cvt_all<<<(XN4 + 3 * WN4 + 255) / 256, 256>>>(
        (const float4*)x, (const float4*)Wg, (const float4*)Wu, (const float4*)Wd);
    gemm1_hmma<<<dim3(I_DIM / 64, MAX_TILES), 256, SM1>>>();
    gemm2_hmma<<<dim3(H_DIM / 128, MAX_TILES), 256, SM2>>>();
    combine_kernel<<<(T_TOK * H_DIM / 4) / 256, 256>>>(rw, (float4*)out);
    (void)in_sizes; (void)n_in; (void)out_size;
}